// round 6
// baseline (speedup 1.0000x reference)
#include <cuda_runtime.h>

#define DEV_INLINE __device__ __forceinline__
using u64 = unsigned long long;

constexpr int B_  = 8;
constexpr int TQ  = 256;
constexpr int TV  = 512;
constexpr int D_  = 256;
constexpr float SCALE2 = 2.8853900817779268f;   // 2*log2(e)
constexpr float LOG2E  = 1.4426950408889634f;

__device__ float g_qproj[B_ * TQ * D_];   // EQ  = 2^{SCALE2*(q@W1+b1)}
__device__ float g_vproj[B_ * TV * D_];   // EV' = 2^{SCALE2*(v@W2+b2) - 16}
__device__ float g_score[B_ * TQ * TV];   // scores, then alignment in-place

DEV_INLINE float fast_ex2(float x) { float y; asm("ex2.approx.f32 %0, %1;" : "=f"(y) : "f"(x)); return y; }

// ---- packed f32x2 helpers ----
DEV_INLINE u64 pk2(float lo, float hi) { u64 r; asm("mov.b64 %0, {%1, %2};" : "=l"(r) : "f"(lo), "f"(hi)); return r; }
DEV_INLINE void upk2(u64 p, float& lo, float& hi) { asm("mov.b64 {%0, %1}, %2;" : "=f"(lo), "=f"(hi) : "l"(p)); }
DEV_INLINE u64 bc2(float x) { u64 r; asm("mov.b64 %0, {%1, %1};" : "=l"(r) : "f"(x)); return r; }
DEV_INLINE u64 add2(u64 a, u64 b) { u64 r; asm("add.rn.f32x2 %0, %1, %2;" : "=l"(r) : "l"(a), "l"(b)); return r; }
DEV_INLINE u64 mul2(u64 a, u64 b) { u64 r; asm("mul.rn.f32x2 %0, %1, %2;" : "=l"(r) : "l"(a), "l"(b)); return r; }
DEV_INLINE u64 fma2(u64 a, u64 b, u64 c) { u64 r; asm("fma.rn.f32x2 %0, %1, %2, %3;" : "=l"(r) : "l"(a), "l"(b), "l"(c)); return r; }

DEV_INLINE u64 rcp2_pair(u64 a) {
    u64 r;
    asm("{\n\t.reg .f32 al, ah, rl, rh;\n\t"
        "mov.b64 {al, ah}, %1;\n\t"
        "rcp.approx.f32 rl, al;\n\t"
        "rcp.approx.f32 rh, ah;\n\t"
        "mov.b64 %0, {rl, rh};\n\t}"
        : "=l"(r) : "l"(a));
    return r;
}

// ---------------------------------------------------------------------------
// K1: projection GEMM + exponential epilogue:
//     P[m][e] = 2^{ SCALE2*(X@W + b)[m][e] + shift }
// ---------------------------------------------------------------------------
__global__ __launch_bounds__(256) void proj_kernel(
    const float* __restrict__ X, const float* __restrict__ W,
    const float* __restrict__ bias, float* __restrict__ P, float shift)
{
    __shared__ float sAT[16][64];
    __shared__ float sB[16][64];
    const int tid = threadIdx.x;
    const int mb = blockIdx.y * 64;
    const int nb = blockIdx.x * 64;
    const int tm = tid >> 4, tn = tid & 15;
    const int arow = tid >> 2, akv = tid & 3;
    const int brow = tid >> 4, bcv = tid & 15;

    u64 acc2[2][4] = {};

    for (int kt = 0; kt < D_; kt += 16) {
        float4 av = *(const float4*)(X + (mb + arow) * D_ + kt + akv * 4);
        float4 bv = *(const float4*)(W + (kt + brow) * D_ + nb + bcv * 4);
        __syncthreads();
        sAT[akv*4+0][arow] = av.x; sAT[akv*4+1][arow] = av.y;
        sAT[akv*4+2][arow] = av.z; sAT[akv*4+3][arow] = av.w;
        *(float4*)&sB[brow][bcv*4] = bv;
        __syncthreads();
        #pragma unroll
        for (int k = 0; k < 16; k++) {
            float2 a01 = *(const float2*)&sAT[k][tm*4];
            float2 a23 = *(const float2*)&sAT[k][tm*4 + 2];
            float4 bq  = *(const float4*)&sB[k][tn*4];
            u64 A01 = pk2(a01.x, a01.y);
            u64 A23 = pk2(a23.x, a23.y);
            u64 B0 = bc2(bq.x), B1 = bc2(bq.y), B2 = bc2(bq.z), B3 = bc2(bq.w);
            acc2[0][0] = fma2(A01, B0, acc2[0][0]);
            acc2[0][1] = fma2(A01, B1, acc2[0][1]);
            acc2[0][2] = fma2(A01, B2, acc2[0][2]);
            acc2[0][3] = fma2(A01, B3, acc2[0][3]);
            acc2[1][0] = fma2(A23, B0, acc2[1][0]);
            acc2[1][1] = fma2(A23, B1, acc2[1][1]);
            acc2[1][2] = fma2(A23, B2, acc2[1][2]);
            acc2[1][3] = fma2(A23, B3, acc2[1][3]);
        }
    }
    float4 bias4 = *(const float4*)(bias + nb + tn*4);
    u64 S2 = pk2(SCALE2, SCALE2);
    u64 BS[4] = { bc2(bias4.x*SCALE2 + shift), bc2(bias4.y*SCALE2 + shift),
                  bc2(bias4.z*SCALE2 + shift), bc2(bias4.w*SCALE2 + shift) };
    #pragma unroll
    for (int ip = 0; ip < 2; ip++) {
        float lo[4], hi[4];
        #pragma unroll
        for (int j = 0; j < 4; j++) {
            u64 r = fma2(acc2[ip][j], S2, BS[j]);
            upk2(r, lo[j], hi[j]);
            lo[j] = fast_ex2(lo[j]);
            hi[j] = fast_ex2(hi[j]);
        }
        *(float4*)(P + (mb + tm*4 + ip*2 + 0) * D_ + nb + tn*4) = make_float4(lo[0], lo[1], lo[2], lo[3]);
        *(float4*)(P + (mb + tm*4 + ip*2 + 1) * D_ + nb + tn*4) = make_float4(hi[0], hi[1], hi[2], hi[3]);
    }
}

// ---------------------------------------------------------------------------
// K2: score = D - 2^-15 * sum acc, acc += quad-rational of w = fma(EQ,EV',2^-16)
// Lanes = q-row pairs (p, p+32). V broadcast hoisted per (vec,jj), reused by
// all 4 q-pairs. Block 64q x 64j, thread 8q x 4j, d-chunks of 64.
// ---------------------------------------------------------------------------
__global__ __launch_bounds__(128, 4) void score_kernel()
{
    __shared__ float sQP[32 * 66 * 2];   // u64-paired Q (float view), row pitch 66 u64
    __shared__ float sV[64][68];         // EV', row pitch 68 floats

    const int tid = threadIdx.x;         // 128
    const int b   = blockIdx.z;
    const int qt  = blockIdx.y;          // 0..3  (TQ/64)
    const int jt  = blockIdx.x;          // 0..7  (TV/64)
    const int qbase = qt * 64, jbase = jt * 64;
    const float* qp = g_qproj + (b * TQ + qbase) * D_;
    const float* vp = g_vproj + (b * TV + jbase) * D_;
    const int tq = tid >> 4;             // 0..7
    const int tj = tid & 15;             // 0..15

    const u64 C16 = bc2(0x1p-16f);
    u64 acc[4][4] = {};                  // [a][j]: qpair p=tq+8a, jj=tj+16j

    for (int dc = 0; dc < D_; dc += 64) {
        __syncthreads();
        #pragma unroll
        for (int i = 0; i < 8; i++) {
            int idx = i * 128 + tid;         // 1024 float4s per 64x64 tile
            int r = idx >> 4, dv = idx & 15;
            *(float4*)&sV[r][dv*4] = *(const float4*)(vp + r * D_ + dc + dv*4);
            float4 q = *(const float4*)(qp + r * D_ + dc + dv*4);
            int p = r & 31, half = r >> 5;
            float* base = &sQP[(p*66 + dv*4)*2 + half];
            base[0] = q.x; base[2] = q.y; base[4] = q.z; base[6] = q.w;
        }
        __syncthreads();

        #pragma unroll
        for (int vec = 0; vec < 16; vec++) {
            u64 vb[4][4];
            #pragma unroll
            for (int j = 0; j < 4; j++) {
                float4 v = *(const float4*)&sV[tj + 16*j][vec*4];
                vb[j][0] = bc2(v.x); vb[j][1] = bc2(v.y);
                vb[j][2] = bc2(v.z); vb[j][3] = bc2(v.w);
            }
            #pragma unroll
            for (int a = 0; a < 4; a++) {
                int p = tq + 8*a;
                const ulonglong2* qrow = (const ulonglong2*)&sQP[(p*66 + vec*4)*2];
                ulonglong2 qlo = qrow[0], qhi = qrow[1];
                u64 q0 = qlo.x, q1 = qlo.y, q2 = qhi.x, q3 = qhi.y;
                #pragma unroll
                for (int j = 0; j < 4; j++) {
                    u64 w0 = fma2(q0, vb[j][0], C16);
                    u64 w1 = fma2(q1, vb[j][1], C16);
                    u64 w2 = fma2(q2, vb[j][2], C16);
                    u64 w3 = fma2(q3, vb[j][3], C16);
                    u64 p12 = mul2(w0, w1);
                    u64 p34 = mul2(w2, w3);
                    u64 num = fma2(p12, add2(w2, w3), mul2(p34, add2(w0, w1)));
                    u64 den = mul2(p12, p34);
                    acc[a][j] = fma2(num, rcp2_pair(den), acc[a][j]);
                }
            }
        }
    }

    #pragma unroll
    for (int a = 0; a < 4; a++) {
        int p = tq + 8*a;
        #pragma unroll
        for (int j = 0; j < 4; j++) {
            float lo, hi; upk2(acc[a][j], lo, hi);
            int jj = jbase + tj + 16*j;
            g_score[(size_t)(b * TQ + qbase + p     ) * TV + jj] = (float)D_ - lo * 0x1p-15f;
            g_score[(size_t)(b * TQ + qbase + p + 32) * TV + jj] = (float)D_ - hi * 0x1p-15f;
        }
    }
}

// ---------------------------------------------------------------------------
// K3: softmax over TV=512 (16-row slab, warp per 2 rows) + transposed output.
// ---------------------------------------------------------------------------
__global__ __launch_bounds__(256) void softmax_kernel(float* __restrict__ out_at)
{
    __shared__ float sm[16][513];
    const int b    = blockIdx.x >> 4;
    const int slab = blockIdx.x & 15;
    const int q0   = slab * 16;
    const int wid  = threadIdx.x >> 5, lane = threadIdx.x & 31;

    #pragma unroll
    for (int rr = 0; rr < 2; rr++) {
        const int r = wid * 2 + rr;
        float* s = g_score + (size_t)(b * TQ + q0 + r) * TV;
        float4 v[4];
        #pragma unroll
        for (int k = 0; k < 4; k++) v[k] = *(const float4*)(s + (k*32 + lane)*4);
        float m = -1e30f;
        #pragma unroll
        for (int k = 0; k < 4; k++)
            m = fmaxf(m, fmaxf(fmaxf(v[k].x, v[k].y), fmaxf(v[k].z, v[k].w)));
        #pragma unroll
        for (int o = 16; o; o >>= 1) m = fmaxf(m, __shfl_xor_sync(0xffffffffu, m, o));

        float4 e[4]; float sum = 0.0f;
        #pragma unroll
        for (int k = 0; k < 4; k++) {
            e[k].x = fast_ex2((v[k].x - m) * LOG2E);
            e[k].y = fast_ex2((v[k].y - m) * LOG2E);
            e[k].z = fast_ex2((v[k].z - m) * LOG2E);
            e[k].w = fast_ex2((v[k].w - m) * LOG2E);
            sum += (e[k].x + e[k].y) + (e[k].z + e[k].w);
        }
        #pragma unroll
        for (int o = 16; o; o >>= 1) sum += __shfl_xor_sync(0xffffffffu, sum, o);
        float inv = 1.0f / sum;

        #pragma unroll
        for (int k = 0; k < 4; k++) {
            float4 a = make_float4(e[k].x*inv, e[k].y*inv, e[k].z*inv, e[k].w*inv);
            *(float4*)(s + (k*32 + lane)*4) = a;
            int col = (k*32 + lane)*4;
            sm[r][col+0] = a.x; sm[r][col+1] = a.y; sm[r][col+2] = a.z; sm[r][col+3] = a.w;
        }
    }
    __syncthreads();

    const int i = lane & 15;
    const int jb = wid * 64 + (lane >> 4) * 32;
    float* dst = out_at + (size_t)(b * TV) * TQ + q0 + i;
    #pragma unroll
    for (int jj = 0; jj < 32; jj++) {
        int j = jb + jj;
        dst[(size_t)j * TQ] = sm[i][j];
    }
}

// ---------------------------------------------------------------------------
// K4: context[b] = alignment[b] @ value[b]; also copies the matching query
// block into out[..][D:2D] (concat fused here).
// ---------------------------------------------------------------------------
__global__ __launch_bounds__(256) void context_kernel(
    const float* __restrict__ value, const float* __restrict__ query,
    float* __restrict__ out)
{
    __shared__ float sAT[16][64];
    __shared__ float sB[16][64];
    const int tid = threadIdx.x;
    const int b  = blockIdx.z;
    const int mb = blockIdx.y * 64;
    const int nb = blockIdx.x * 64;
    const float* A = g_score + (size_t)b * TQ * TV;
    const float* V = value + (size_t)b * TV * D_;
    float* C = out + (size_t)b * TQ * (2 * D_);
    const int tm = tid >> 4, tn = tid & 15;
    const int arow = tid >> 2, akv = tid & 3;
    const int brow = tid >> 4, bcv = tid & 15;

    u64 acc2[2][4] = {};

    for (int kt = 0; kt < TV; kt += 16) {
        float4 av = *(const float4*)(A + (mb + arow) * TV + kt + akv * 4);
        float4 bv = *(const float4*)(V + (kt + brow) * D_ + nb + bcv * 4);
        __syncthreads();
        sAT[akv*4+0][arow] = av.x; sAT[akv*4+1][arow] = av.y;
        sAT[akv*4+2][arow] = av.z; sAT[akv*4+3][arow] = av.w;
        *(float4*)&sB[brow][bcv*4] = bv;
        __syncthreads();
        #pragma unroll
        for (int k = 0; k < 16; k++) {
            float2 a01 = *(const float2*)&sAT[k][tm*4];
            float2 a23 = *(const float2*)&sAT[k][tm*4 + 2];
            float4 bq  = *(const float4*)&sB[k][tn*4];
            u64 A01 = pk2(a01.x, a01.y);
            u64 A23 = pk2(a23.x, a23.y);
            u64 B0 = bc2(bq.x), B1 = bc2(bq.y), B2 = bc2(bq.z), B3 = bc2(bq.w);
            acc2[0][0] = fma2(A01, B0, acc2[0][0]);
            acc2[0][1] = fma2(A01, B1, acc2[0][1]);
            acc2[0][2] = fma2(A01, B2, acc2[0][2]);
            acc2[0][3] = fma2(A01, B3, acc2[0][3]);
            acc2[1][0] = fma2(A23, B0, acc2[1][0]);
            acc2[1][1] = fma2(A23, B1, acc2[1][1]);
            acc2[1][2] = fma2(A23, B2, acc2[1][2]);
            acc2[1][3] = fma2(A23, B3, acc2[1][3]);
        }
    }
    #pragma unroll
    for (int ip = 0; ip < 2; ip++) {
        float lo[4], hi[4];
        #pragma unroll
        for (int j = 0; j < 4; j++) upk2(acc2[ip][j], lo[j], hi[j]);
        *(float4*)(C + (mb + tm*4 + ip*2 + 0) * (2 * D_) + nb + tn*4) = make_float4(lo[0], lo[1], lo[2], lo[3]);
        *(float4*)(C + (mb + tm*4 + ip*2 + 1) * (2 * D_) + nb + tn*4) = make_float4(hi[0], hi[1], hi[2], hi[3]);
    }

    // fused query concat: out[b][mb..][D + nb..] = query[b][mb..][nb..]
    const float* Q = query + (size_t)b * TQ * D_;
    #pragma unroll
    for (int i = 0; i < 4; i++) {
        int idx = i * 256 + tid;            // 1024 float4s in 64x64 block
        int r = idx >> 4, c = idx & 15;
        *(float4*)(C + (mb + r) * (2 * D_) + D_ + nb + c*4) =
            *(const float4*)(Q + (mb + r) * D_ + nb + c*4);
    }
}

// ---------------------------------------------------------------------------
extern "C" void kernel_launch(void* const* d_in, const int* in_sizes, int n_in,
                              void* d_out, int out_size)
{
    const float* query = (const float*)d_in[0];   // [8,256,256]
    const float* value = (const float*)d_in[1];   // [8,512,256]
    const float* W1    = (const float*)d_in[2];   // [256,256]
    const float* b1    = (const float*)d_in[3];   // [256]
    const float* W2    = (const float*)d_in[4];   // [256,256]
    const float* b2    = (const float*)d_in[5];   // [256]
    float* out = (float*)d_out;

    void *qp_, *vp_;
    cudaGetSymbolAddress(&qp_, g_qproj);
    cudaGetSymbolAddress(&vp_, g_vproj);

    proj_kernel<<<dim3(4, 32), 256>>>(query, W1, b1, (float*)qp_,  0.0f);
    proj_kernel<<<dim3(4, 64), 256>>>(value, W2, b2, (float*)vp_, -16.0f);
    score_kernel<<<dim3(8, 4, 8), 128>>>();
    softmax_kernel<<<128, 256>>>(out + B_ * TQ * 2 * D_);
    context_kernel<<<dim3(4, 4, 8), 256>>>(value, query, out);
}